// round 14
// baseline (speedup 1.0000x reference)
#include <cuda_runtime.h>
#include <cuda_fp16.h>
#include <cstdint>

// ---------------------------------------------------------------------------
// Problem constants
// ---------------------------------------------------------------------------
#define BB    128
#define CIN   96
#define HH    63
#define WW    63
#define COUT  256
#define HO    30
#define WO    30
#define HID   24
#define TEMPR 31.0f

#define KDIM  2400
#define PDIM  900
#define PPAD  1024

// batch pipeline
#define NCH   4
#define CHB   (BB / NCH)                // 32 samples per chunk

// GEMM tiling: CTA 128(M) x 96(N), 8 warps at 64x24, fp16, KSTEP=48
#define KSTEP   48
#define NKIT    (KDIM / KSTEP)          // 50
#define MT      128
#define NT      96
#define NPT     10
#define STAGES  4
#define AROWU   28
#define ATILE_U (MT * AROWU)
#define BTILE_U (NT * AROWU)
#define STAGE_U (ATILE_U + BTILE_U)
#define SMEM_B  (STAGES * STAGE_U * 4)  // 100352 bytes
#define BCHUNKS (NT * 6)

// im2col: block = (ohp, quarter, b); 2 oh per block, 7-row slab
#define CIQ     24
#define QK      (CIQ * 25)
#define QK2     (QK / 2)
#define QC4     (QK2 / 4)
#define OHB     2
#define SROWS   7
#define SROW    65
#define SLABF   (CIQ * SROWS * SROW)

// ---------------------------------------------------------------------------
// Device scratch
// ---------------------------------------------------------------------------
__device__ float g_pooled[BB * CIN];
__device__ float g_att[BB * 2];
__device__ __align__(256) __half g_wh[(size_t)BB * COUT * KDIM];
__device__ __align__(256) __half g_xh[(size_t)BB * PPAD * KDIM];

// ---------------------------------------------------------------------------
// Helpers
// ---------------------------------------------------------------------------
__device__ __forceinline__ uint32_t smem_u32(const void* p) {
    uint32_t a;
    asm("{ .reg .u64 t; cvta.to.shared.u64 t, %1; cvt.u32.u64 %0, t; }"
        : "=r"(a) : "l"(p));
    return a;
}
__device__ __forceinline__ void cp16(uint32_t dst, const void* src) {
    asm volatile("cp.async.cg.shared.global [%0], [%1], 16;"
                 :: "r"(dst), "l"(src) : "memory");
}
__device__ __forceinline__ void cp_commit() {
    asm volatile("cp.async.commit_group;" ::: "memory");
}
__device__ __forceinline__ void cp_wait2() {
    asm volatile("cp.async.wait_group 2;" ::: "memory");
}
__device__ __forceinline__ void ldsm4(uint32_t* r, uint32_t addr) {
    asm volatile("ldmatrix.sync.aligned.m8n8.x4.shared.b16 {%0,%1,%2,%3}, [%4];"
                 : "=r"(r[0]), "=r"(r[1]), "=r"(r[2]), "=r"(r[3]) : "r"(addr));
}
__device__ __forceinline__ void ldsm2(uint32_t* r, uint32_t addr) {
    asm volatile("ldmatrix.sync.aligned.m8n8.x2.shared.b16 {%0,%1}, [%2];"
                 : "=r"(r[0]), "=r"(r[1]) : "r"(addr));
}
__device__ __forceinline__ void mma_f16(float* d, const uint32_t* a,
                                        const uint32_t* b) {
    asm volatile(
        "mma.sync.aligned.m16n8k16.row.col.f32.f16.f16.f32 "
        "{%0,%1,%2,%3}, {%4,%5,%6,%7}, {%8,%9}, {%0,%1,%2,%3};"
        : "+f"(d[0]), "+f"(d[1]), "+f"(d[2]), "+f"(d[3])
        : "r"(a[0]), "r"(a[1]), "r"(a[2]), "r"(a[3]), "r"(b[0]), "r"(b[1]));
}
__device__ __forceinline__ uint32_t pack_h2(float v0, float v1) {
    __half2 h;
    h.x = __float2half_rn(v0);
    h.y = __float2half_rn(v1);
    return *(uint32_t*)&h;
}

// ---------------------------------------------------------------------------
// Kernel 1: global average pool (chunked: b = blockIdx.y + b0)
// ---------------------------------------------------------------------------
__global__ void pool_kernel(const float* __restrict__ x, int b0) {
    const int ci = blockIdx.x;
    const int b  = blockIdx.y + b0;
    const float* p = x + ((size_t)(b * CIN + ci)) * (HH * WW);
    float s = 0.f;
    for (int i = threadIdx.x; i < HH * WW; i += blockDim.x) s += p[i];
    __shared__ float red[32];
    #pragma unroll
    for (int o = 16; o; o >>= 1) s += __shfl_down_sync(0xffffffffu, s, o);
    if ((threadIdx.x & 31) == 0) red[threadIdx.x >> 5] = s;
    __syncthreads();
    if (threadIdx.x < 32) {
        s = (threadIdx.x < (blockDim.x >> 5)) ? red[threadIdx.x] : 0.f;
        #pragma unroll
        for (int o = 16; o; o >>= 1) s += __shfl_down_sync(0xffffffffu, s, o);
        if (threadIdx.x == 0) g_pooled[b * CIN + ci] = s * (1.0f / (HH * WW));
    }
}

// ---------------------------------------------------------------------------
// Kernel 2: attention MLP + softmax (chunked: thread = sample within chunk)
// ---------------------------------------------------------------------------
__global__ void att_kernel(const float* __restrict__ w1,
                           const float* __restrict__ w2, int b0) {
    const int b = threadIdx.x + b0;
    if (threadIdx.x >= CHB) return;
    float pooled[CIN];
    #pragma unroll 8
    for (int i = 0; i < CIN; i++) pooled[i] = g_pooled[b * CIN + i];
    float l0 = 0.f, l1 = 0.f;
    for (int j = 0; j < HID; j++) {
        float h = 0.f;
        #pragma unroll 8
        for (int i = 0; i < CIN; i++) h += pooled[i] * w1[j * CIN + i];
        h = fmaxf(h, 0.f);
        l0 += h * w2[0 * HID + j];
        l1 += h * w2[1 * HID + j];
    }
    l0 *= (1.0f / TEMPR);
    l1 *= (1.0f / TEMPR);
    const float m  = fmaxf(l0, l1);
    const float e0 = __expf(l0 - m);
    const float e1 = __expf(l1 - m);
    const float inv = 1.0f / (e0 + e1);
    g_att[b * 2 + 0] = e0 * inv;
    g_att[b * 2 + 1] = e1 * inv;
}

// ---------------------------------------------------------------------------
// Kernel 3: mixed weight -> fp16 (chunked)
// ---------------------------------------------------------------------------
__global__ void wmix_kernel(const float* __restrict__ wc,
                            const float* __restrict__ we, int b0) {
    const int co = blockIdx.x;
    const int b  = blockIdx.y + b0;
    const float a0 = g_att[2 * b], a1 = g_att[2 * b + 1];
    uint32_t* dst = (uint32_t*)(g_wh + ((size_t)b * COUT + co) * KDIM);
    const float* pc = wc + (size_t)co * KDIM;
    const float* pe = we + (size_t)co * KDIM;
    for (int k2 = threadIdx.x; k2 < KDIM / 2; k2 += blockDim.x) {
        const int k = k2 * 2;
        dst[k2] = pack_h2(a0 * pc[k] + a1 * pe[k],
                          a0 * pc[k + 1] + a1 * pe[k + 1]);
    }
}

// ---------------------------------------------------------------------------
// Kernel 4: im2col -> fp16 (chunked: b = blockIdx.z + b0)
// ---------------------------------------------------------------------------
__global__ void __launch_bounds__(256) im2col_kernel(const float* __restrict__ x,
                                                     int b0) {
    __shared__ float slab[SLABF];
    __shared__ __align__(16) int soff[QK];

    const int ohp = blockIdx.x;
    const int q   = blockIdx.y;
    const int b   = blockIdx.z + b0;
    const int ci0 = q * CIQ;
    const int tid = threadIdx.x;
    const int wid = tid >> 5, lane = tid & 31;

    for (int j = tid; j < QK; j += 256) {
        const int cl = j / 25, t = j - cl * 25;
        const int kh = t / 5, kw = t - kh * 5;
        soff[j] = (cl * SROWS + kh) * SROW + kw;
    }

    const float* xb = x + ((size_t)b * CIN + ci0) * (HH * WW) + (size_t)(ohp * 4) * WW;
    for (int row = wid; row < CIQ * SROWS; row += 8) {
        const int cl = row / SROWS, rr = row - cl * SROWS;
        const float* src = xb + (size_t)cl * (HH * WW) + rr * WW;
        float* dstr = slab + row * SROW;
        if (lane < 63) dstr[lane] = src[lane];
        if (lane < 31) dstr[lane + 32] = src[lane + 32];
    }
    __syncthreads();

    uint32_t* dst0 = (uint32_t*)(g_xh + ((size_t)b * PPAD + ohp * OHB * WO) * KDIM)
                     + q * QK2;
    for (int idx = tid; idx < OHB * WO * QC4; idx += 256) {
        const int owc = idx / QC4;
        const int c4  = idx - owc * QC4;
        const int dl  = owc / WO;
        const int ow  = owc - dl * WO;
        const int4 o0 = *(const int4*)&soff[c4 * 8];
        const int4 o1 = *(const int4*)&soff[c4 * 8 + 4];
        const float* sl = slab + dl * 2 * SROW + ow * 2;
        uint4 v;
        v.x = pack_h2(sl[o0.x], sl[o0.y]);
        v.y = pack_h2(sl[o0.z], sl[o0.w]);
        v.z = pack_h2(sl[o1.x], sl[o1.y]);
        v.w = pack_h2(sl[o1.z], sl[o1.w]);
        *(uint4*)&dst0[(size_t)owc * (KDIM / 2) + c4 * 4] = v;
    }
}

// ---------------------------------------------------------------------------
// Kernel 5: fp16 mma.sync GEMM (chunked: b = blockIdx.y + b0)
// ---------------------------------------------------------------------------
__global__ void __launch_bounds__(256, 2)
gemm_kernel(const float* __restrict__ cb, const float* __restrict__ eb,
            float* __restrict__ out, int b0)
{
    extern __shared__ uint32_t sm[];
    const int b   = blockIdx.y + b0;
    const int ct  = blockIdx.x / NPT;
    const int pt  = blockIdx.x - ct * NPT;
    const int co0 = ct * MT;
    const int p0  = pt * NT;

    const int tid  = threadIdx.x;
    const int wid  = tid >> 5;
    const int lane = tid & 31;
    const int wm   = wid & 1;
    const int wn   = wid >> 1;
    const int g    = lane >> 2;
    const int t    = lane & 3;

    const __half* gA = g_wh + ((size_t)b * COUT + co0) * KDIM;
    const __half* gB = g_xh + ((size_t)b * PPAD + p0) * KDIM;

    const uint32_t smbase = smem_u32(sm);

    uint32_t aoff[4];
    #pragma unroll
    for (int m = 0; m < 4; m++) {
        const int row = wm * 64 + m * 16 + (lane & 15);
        aoff[m] = (uint32_t)(row * AROWU + (lane >> 4) * 4) * 4;
    }
    uint32_t boff4;
    {
        const int row = wn * 24 + ((lane >> 4) << 3) + (lane & 7);
        boff4 = (uint32_t)(ATILE_U + row * AROWU + ((lane >> 3) & 1) * 4) * 4;
    }
    uint32_t boff2;
    {
        const int row = wn * 24 + 16 + (lane & 7);
        boff2 = (uint32_t)(ATILE_U + row * AROWU + ((lane >> 3) & 1) * 4) * 4;
    }

    float acc[4][3][4];
    #pragma unroll
    for (int m = 0; m < 4; m++)
        #pragma unroll
        for (int n = 0; n < 3; n++)
            #pragma unroll
            for (int r = 0; r < 4; r++) acc[m][n][r] = 0.f;

    #pragma unroll
    for (int s = 0; s < 3; s++) {
        const int k0 = s * KSTEP;
        const uint32_t ab = smbase + (uint32_t)(s * STAGE_U) * 4;
        const uint32_t bbs = ab + ATILE_U * 4;
        #pragma unroll
        for (int j = 0; j < 3; j++) {
            const int c = tid + 256 * j;
            const int r = c / 6, sg = c - r * 6;
            cp16(ab + (uint32_t)(r * AROWU + sg * 4) * 4, gA + (size_t)r * KDIM + k0 + sg * 8);
        }
        #pragma unroll
        for (int j = 0; j < 3; j++) {
            const int c = tid + 256 * j;
            if (c < BCHUNKS) {
                const int r = c / 6, sg = c - r * 6;
                cp16(bbs + (uint32_t)(r * AROWU + sg * 4) * 4, gB + (size_t)r * KDIM + k0 + sg * 8);
            }
        }
        cp_commit();
    }

    for (int it = 0; it < NKIT; it++) {
        cp_wait2();
        __syncthreads();

        if (it + 3 < NKIT) {
            const int s = (it + 3) & 3;
            const int k0 = (it + 3) * KSTEP;
            const uint32_t ab = smbase + (uint32_t)(s * STAGE_U) * 4;
            const uint32_t bbs = ab + ATILE_U * 4;
            #pragma unroll
            for (int j = 0; j < 3; j++) {
                const int c = tid + 256 * j;
                const int r = c / 6, sg = c - r * 6;
                cp16(ab + (uint32_t)(r * AROWU + sg * 4) * 4, gA + (size_t)r * KDIM + k0 + sg * 8);
            }
            #pragma unroll
            for (int j = 0; j < 3; j++) {
                const int c = tid + 256 * j;
                if (c < BCHUNKS) {
                    const int r = c / 6, sg = c - r * 6;
                    cp16(bbs + (uint32_t)(r * AROWU + sg * 4) * 4, gB + (size_t)r * KDIM + k0 + sg * 8);
                }
            }
        }
        cp_commit();

        const uint32_t stoff = smbase + (uint32_t)((it & 3) * STAGE_U) * 4;

        #pragma unroll
        for (int kk = 0; kk < 3; kk++) {
            const uint32_t kb = stoff + kk * 32;
            uint32_t afr[4][4];
            #pragma unroll
            for (int m = 0; m < 4; m++)
                ldsm4(afr[m], kb + aoff[m]);
            uint32_t bfr[3][2];
            {
                uint32_t r4[4];
                ldsm4(r4, kb + boff4);
                bfr[0][0] = r4[0]; bfr[0][1] = r4[1];
                bfr[1][0] = r4[2]; bfr[1][1] = r4[3];
                ldsm2(bfr[2], kb + boff2);
            }
            #pragma unroll
            for (int m = 0; m < 4; m++)
                #pragma unroll
                for (int n = 0; n < 3; n++)
                    mma_f16(acc[m][n], afr[m], bfr[n]);
        }
    }

    const float a0 = g_att[2 * b], a1 = g_att[2 * b + 1];
    #pragma unroll
    for (int m = 0; m < 4; m++) {
        const int co_lo = co0 + wm * 64 + m * 16 + g;
        const int co_hi = co_lo + 8;
        const float bias_lo = a0 * cb[co_lo] + a1 * eb[co_lo];
        const float bias_hi = a0 * cb[co_hi] + a1 * eb[co_hi];
        float* op_lo = out + ((size_t)b * COUT + co_lo) * PDIM;
        float* op_hi = out + ((size_t)b * COUT + co_hi) * PDIM;
        #pragma unroll
        for (int n = 0; n < 3; n++) {
            const int p = p0 + wn * 24 + n * 8 + t * 2;
            if (p < PDIM) {
                float2 v0 = make_float2(acc[m][n][0] + bias_lo, acc[m][n][1] + bias_lo);
                float2 v1 = make_float2(acc[m][n][2] + bias_hi, acc[m][n][3] + bias_hi);
                *(float2*)(op_lo + p) = v0;
                *(float2*)(op_hi + p) = v1;
            }
        }
    }
}

// ---------------------------------------------------------------------------
// Host launch: batch-chunk pipeline.
//   s2  : per-chunk pool -> att -> wmix  (records ev_w[c])
//   main: im2col chunks serially         (records ev_i[c])
//   s3  : gemm chunk c after ev_w[c] + ev_i[c]
// Streams/events created once at first (uncaptured) call.
// ---------------------------------------------------------------------------
extern "C" void kernel_launch(void* const* d_in, const int* in_sizes, int n_in,
                              void* d_out, int out_size) {
    (void)in_sizes; (void)n_in; (void)out_size;
    const float* x  = (const float*)d_in[0];
    const float* wc = (const float*)d_in[1];
    const float* cb = (const float*)d_in[2];
    const float* we = (const float*)d_in[3];
    const float* eb = (const float*)d_in[4];
    const float* w1 = (const float*)d_in[5];
    const float* w2 = (const float*)d_in[6];
    float* out = (float*)d_out;

    static cudaStream_t s2 = nullptr, s3 = nullptr;
    static cudaEvent_t ev_root = nullptr, ev_done = nullptr;
    static cudaEvent_t ev_w[NCH], ev_i[NCH];
    if (s2 == nullptr) {
        cudaStreamCreateWithFlags(&s2, cudaStreamNonBlocking);
        cudaStreamCreateWithFlags(&s3, cudaStreamNonBlocking);
        cudaEventCreateWithFlags(&ev_root, cudaEventDisableTiming);
        cudaEventCreateWithFlags(&ev_done, cudaEventDisableTiming);
        for (int c = 0; c < NCH; c++) {
            cudaEventCreateWithFlags(&ev_w[c], cudaEventDisableTiming);
            cudaEventCreateWithFlags(&ev_i[c], cudaEventDisableTiming);
        }
        cudaFuncSetAttribute(gemm_kernel,
                             cudaFuncAttributeMaxDynamicSharedMemorySize, SMEM_B);
    }

    cudaEventRecord(ev_root, 0);
    cudaStreamWaitEvent(s2, ev_root, 0);
    cudaStreamWaitEvent(s3, ev_root, 0);

    // s2: per-chunk attention/weight-mix chain
    for (int c = 0; c < NCH; c++) {
        const int b0 = c * CHB;
        pool_kernel<<<dim3(CIN, CHB), 256, 0, s2>>>(x, b0);
        att_kernel<<<1, CHB, 0, s2>>>(w1, w2, b0);
        wmix_kernel<<<dim3(COUT, CHB), 256, 0, s2>>>(wc, we, b0);
        cudaEventRecord(ev_w[c], s2);
    }

    // main: im2col chunks
    for (int c = 0; c < NCH; c++) {
        im2col_kernel<<<dim3(HO / OHB, 4, CHB), 256>>>(x, c * CHB);
        cudaEventRecord(ev_i[c], 0);
    }

    // s3: gemm chunks, each gated on its inputs
    for (int c = 0; c < NCH; c++) {
        cudaStreamWaitEvent(s3, ev_w[c], 0);
        cudaStreamWaitEvent(s3, ev_i[c], 0);
        gemm_kernel<<<dim3(2 * NPT, CHB), 256, SMEM_B, s3>>>(cb, eb, out, c * CHB);
    }

    cudaEventRecord(ev_done, s3);
    cudaStreamWaitEvent(0, ev_done, 0);
}

// round 16
// speedup vs baseline: 1.3149x; 1.3149x over previous
#include <cuda_runtime.h>
#include <cuda_fp16.h>
#include <cstdint>

// ---------------------------------------------------------------------------
// Problem constants
// ---------------------------------------------------------------------------
#define BB    128
#define CIN   96
#define HH    63
#define WW    63
#define COUT  256
#define HO    30
#define WO    30
#define HID   24
#define TEMPR 31.0f

#define KDIM  2400
#define PDIM  900
#define PPAD  1024

// GEMM tiling: CTA 128(M) x 96(N), 8 warps at 64x24, fp16, KSTEP=48
#define KSTEP   48
#define NKIT    (KDIM / KSTEP)          // 50
#define MT      128
#define NT      96
#define NPT     10
#define STAGES  4
#define AROWU   28
#define ATILE_U (MT * AROWU)
#define BTILE_U (NT * AROWU)
#define STAGE_U (ATILE_U + BTILE_U)
#define SMEM_B  (STAGES * STAGE_U * 4)  // 100352 bytes
#define BCHUNKS (NT * 6)

// im2col: block = (ohp, quarter, b); 2 oh per block; fp16 slab, permuted K.
// Per-quarter word layout (u32, 300 words): [240 aligned pair-words][60 kw4 words]
#define CIQ     24
#define QK2     300                     // u32 words per quarter
#define OHB     2
#define SROWS   7
#define SROWH   66                      // slab row stride in fp16 (33 words, odd)
#define SLABH   (CIQ * SROWS * SROWH)   // 11088 fp16

// ---------------------------------------------------------------------------
// Device scratch
// ---------------------------------------------------------------------------
__device__ float g_pooled[BB * CIN];
__device__ float g_att[BB * 2];
__device__ __align__(256) __half g_wh[(size_t)BB * COUT * KDIM];
__device__ __align__(256) __half g_xh[(size_t)BB * PPAD * KDIM];

// ---------------------------------------------------------------------------
// Helpers
// ---------------------------------------------------------------------------
__device__ __forceinline__ uint32_t smem_u32(const void* p) {
    uint32_t a;
    asm("{ .reg .u64 t; cvta.to.shared.u64 t, %1; cvt.u32.u64 %0, t; }"
        : "=r"(a) : "l"(p));
    return a;
}
__device__ __forceinline__ void cp16(uint32_t dst, const void* src) {
    asm volatile("cp.async.cg.shared.global [%0], [%1], 16;"
                 :: "r"(dst), "l"(src) : "memory");
}
__device__ __forceinline__ void cp_commit() {
    asm volatile("cp.async.commit_group;" ::: "memory");
}
__device__ __forceinline__ void cp_wait2() {
    asm volatile("cp.async.wait_group 2;" ::: "memory");
}
__device__ __forceinline__ void ldsm4(uint32_t* r, uint32_t addr) {
    asm volatile("ldmatrix.sync.aligned.m8n8.x4.shared.b16 {%0,%1,%2,%3}, [%4];"
                 : "=r"(r[0]), "=r"(r[1]), "=r"(r[2]), "=r"(r[3]) : "r"(addr));
}
__device__ __forceinline__ void ldsm2(uint32_t* r, uint32_t addr) {
    asm volatile("ldmatrix.sync.aligned.m8n8.x2.shared.b16 {%0,%1}, [%2];"
                 : "=r"(r[0]), "=r"(r[1]) : "r"(addr));
}
__device__ __forceinline__ void mma_f16(float* d, const uint32_t* a,
                                        const uint32_t* b) {
    asm volatile(
        "mma.sync.aligned.m16n8k16.row.col.f32.f16.f16.f32 "
        "{%0,%1,%2,%3}, {%4,%5,%6,%7}, {%8,%9}, {%0,%1,%2,%3};"
        : "+f"(d[0]), "+f"(d[1]), "+f"(d[2]), "+f"(d[3])
        : "r"(a[0]), "r"(a[1]), "r"(a[2]), "r"(a[3]), "r"(b[0]), "r"(b[1]));
}
__device__ __forceinline__ uint32_t pack_h2(float v0, float v1) {
    __half2 h;
    h.x = __float2half_rn(v0);
    h.y = __float2half_rn(v1);
    return *(uint32_t*)&h;
}

// word (0..299 within quarter q) -> original k pair (ka, kb)
__device__ __forceinline__ void word_to_kpair(int q, int wq, int* ka, int* kb) {
    if (wq < 240) {
        const int ch = wq / 10, r = wq - ch * 10;
        const int kh = r >> 1, kp = r & 1;
        const int k0 = (q * CIQ + ch) * 25 + kh * 5 + 2 * kp;
        *ka = k0; *kb = k0 + 1;
    } else {
        const int t = wq - 240;
        const int u = 2 * t, u2 = 2 * t + 1;
        *ka = (q * CIQ + u / 5) * 25 + (u % 5) * 5 + 4;
        *kb = (q * CIQ + u2 / 5) * 25 + (u2 % 5) * 5 + 4;
    }
}

// ---------------------------------------------------------------------------
// Kernel 1: global average pool
// ---------------------------------------------------------------------------
__global__ void pool_kernel(const float* __restrict__ x) {
    const int ci = blockIdx.x;
    const int b  = blockIdx.y;
    const float* p = x + ((size_t)(b * CIN + ci)) * (HH * WW);
    float s = 0.f;
    for (int i = threadIdx.x; i < HH * WW; i += blockDim.x) s += p[i];
    __shared__ float red[32];
    #pragma unroll
    for (int o = 16; o; o >>= 1) s += __shfl_down_sync(0xffffffffu, s, o);
    if ((threadIdx.x & 31) == 0) red[threadIdx.x >> 5] = s;
    __syncthreads();
    if (threadIdx.x < 32) {
        s = (threadIdx.x < (blockDim.x >> 5)) ? red[threadIdx.x] : 0.f;
        #pragma unroll
        for (int o = 16; o; o >>= 1) s += __shfl_down_sync(0xffffffffu, s, o);
        if (threadIdx.x == 0) g_pooled[b * CIN + ci] = s * (1.0f / (HH * WW));
    }
}

// ---------------------------------------------------------------------------
// Kernel 2: attention MLP + softmax
// ---------------------------------------------------------------------------
__global__ void att_kernel(const float* __restrict__ w1,
                           const float* __restrict__ w2) {
    const int b = threadIdx.x;
    if (b >= BB) return;
    float pooled[CIN];
    #pragma unroll 8
    for (int i = 0; i < CIN; i++) pooled[i] = g_pooled[b * CIN + i];
    float l0 = 0.f, l1 = 0.f;
    for (int j = 0; j < HID; j++) {
        float h = 0.f;
        #pragma unroll 8
        for (int i = 0; i < CIN; i++) h += pooled[i] * w1[j * CIN + i];
        h = fmaxf(h, 0.f);
        l0 += h * w2[0 * HID + j];
        l1 += h * w2[1 * HID + j];
    }
    l0 *= (1.0f / TEMPR);
    l1 *= (1.0f / TEMPR);
    const float m  = fmaxf(l0, l1);
    const float e0 = __expf(l0 - m);
    const float e1 = __expf(l1 - m);
    const float inv = 1.0f / (e0 + e1);
    g_att[b * 2 + 0] = e0 * inv;
    g_att[b * 2 + 1] = e1 * inv;
}

// ---------------------------------------------------------------------------
// Kernel 3: mixed weight -> fp16, PERMUTED K word layout (matches g_xh)
// ---------------------------------------------------------------------------
__global__ void wmix_kernel(const float* __restrict__ wc,
                            const float* __restrict__ we) {
    const int co = blockIdx.x;
    const int b  = blockIdx.y;
    const float a0 = g_att[2 * b], a1 = g_att[2 * b + 1];
    uint32_t* dst = (uint32_t*)(g_wh + ((size_t)b * COUT + co) * KDIM);
    const float* pc = wc + (size_t)co * KDIM;
    const float* pe = we + (size_t)co * KDIM;
    for (int w = threadIdx.x; w < KDIM / 2; w += blockDim.x) {
        const int q = w / QK2, wq = w - q * QK2;
        int ka, kb;
        word_to_kpair(q, wq, &ka, &kb);
        dst[w] = pack_h2(a0 * pc[ka] + a1 * pe[ka],
                         a0 * pc[kb] + a1 * pe[kb]);
    }
}

// ---------------------------------------------------------------------------
// Kernel 4: im2col -> fp16, permuted K.  Block = (ohp, quarter, b).
// fp16 slab (22KB); 80% of words are single aligned LDS.32 copies.
// ---------------------------------------------------------------------------
__global__ void __launch_bounds__(256) im2col_kernel(const float* __restrict__ x) {
    __shared__ __align__(4) __half slabh[SLABH];
    __shared__ ushort4 a_lut[60];       // word-offsets (u32 units) for aligned block
    __shared__ ushort2 t_lut[60];       // fp16-offsets for kw4 tail pairs

    const int ohp = blockIdx.x;
    const int q   = blockIdx.y;
    const int b   = blockIdx.z;
    const int ci0 = q * CIQ;
    const int tid = threadIdx.x;
    const int wid = tid >> 5, lane = tid & 31;

    // build LUTs
    for (int i = tid; i < 60; i += 256) {
        ushort4 e;
        #pragma unroll
        for (int j = 0; j < 4; j++) {
            const int w = i * 4 + j;
            const int ch = w / 10, r = w - ch * 10;
            const int kh = r >> 1, kp = r & 1;
            const unsigned short v = (unsigned short)((ch * SROWS + kh) * (SROWH / 2) + kp);
            if (j == 0) e.x = v; else if (j == 1) e.y = v;
            else if (j == 2) e.z = v; else e.w = v;
        }
        a_lut[i] = e;
        const int u = 2 * i, u2 = 2 * i + 1;
        ushort2 te;
        te.x = (unsigned short)(((u / 5)  * SROWS + (u  % 5)) * SROWH + 4);
        te.y = (unsigned short)(((u2 / 5) * SROWS + (u2 % 5)) * SROWH + 4);
        t_lut[i] = te;
    }

    // stage slab: CIQ*7 rows of 63 fp16 (converted from x)
    const float* xb = x + ((size_t)b * CIN + ci0) * (HH * WW) + (size_t)(ohp * 4) * WW;
    for (int row = wid; row < CIQ * SROWS; row += 8) {
        const int cl = row / SROWS, rr = row - cl * SROWS;
        const float* src = xb + (size_t)cl * (HH * WW) + rr * WW;
        __half* dstr = slabh + row * SROWH;
        if (lane < 63) dstr[lane] = __float2half_rn(src[lane]);
        if (lane < 31) dstr[lane + 32] = __float2half_rn(src[lane + 32]);
    }
    __syncthreads();

    const uint32_t* slab32 = (const uint32_t*)slabh;
    const unsigned short* s16 = (const unsigned short*)slabh;
    uint32_t* dst0 = (uint32_t*)(g_xh + ((size_t)b * PPAD + ohp * OHB * WO) * KDIM)
                     + q * QK2;

    // phase 1: aligned block — 60 owc x 60 uint4 chunks, 4 LDS.32 + 1 STG.128
    for (int idx = tid; idx < OHB * WO * 60; idx += 256) {
        const int owc = idx / 60;
        const int c4  = idx - owc * 60;
        const int dl  = owc / WO;
        const int ow  = owc - dl * WO;
        const int off = dl * SROWH + ow;          // u32 units (dl*2 rows = 66 words)
        const ushort4 e = a_lut[c4];
        uint4 v;
        v.x = slab32[e.x + off];
        v.y = slab32[e.y + off];
        v.z = slab32[e.z + off];
        v.w = slab32[e.w + off];
        *(uint4*)&dst0[(size_t)owc * (KDIM / 2) + c4 * 4] = v;
    }

    // phase 2: kw4 tail — 60 owc x 15 uint4 chunks, 8 LDS.U16 + 1 STG.128
    for (int idx = tid; idx < OHB * WO * 15; idx += 256) {
        const int owc = idx / 15;
        const int c4t = idx - owc * 15;
        const int dl  = owc / WO;
        const int ow  = owc - dl * WO;
        const int off2 = dl * 2 * SROWH + 2 * ow; // fp16 units
        uint4 v;
        #pragma unroll
        for (int j = 0; j < 4; j++) {
            const ushort2 te = t_lut[c4t * 4 + j];
            const uint32_t lo = s16[te.x + off2];
            const uint32_t hi = s16[te.y + off2];
            ((uint32_t*)&v)[j] = lo | (hi << 16);
        }
        *(uint4*)&dst0[(size_t)owc * (KDIM / 2) + 240 + c4t * 4] = v;
    }
}

// ---------------------------------------------------------------------------
// Kernel 5: fp16 mma.sync GEMM (unchanged; K order opaque).
// ---------------------------------------------------------------------------
__global__ void __launch_bounds__(256, 2)
gemm_kernel(const float* __restrict__ cb, const float* __restrict__ eb,
            float* __restrict__ out)
{
    extern __shared__ uint32_t sm[];
    const int b   = blockIdx.y;
    const int ct  = blockIdx.x / NPT;
    const int pt  = blockIdx.x - ct * NPT;
    const int co0 = ct * MT;
    const int p0  = pt * NT;

    const int tid  = threadIdx.x;
    const int wid  = tid >> 5;
    const int lane = tid & 31;
    const int wm   = wid & 1;
    const int wn   = wid >> 1;
    const int g    = lane >> 2;
    const int t    = lane & 3;

    const __half* gA = g_wh + ((size_t)b * COUT + co0) * KDIM;
    const __half* gB = g_xh + ((size_t)b * PPAD + p0) * KDIM;

    const uint32_t smbase = smem_u32(sm);

    uint32_t aoff[4];
    #pragma unroll
    for (int m = 0; m < 4; m++) {
        const int row = wm * 64 + m * 16 + (lane & 15);
        aoff[m] = (uint32_t)(row * AROWU + (lane >> 4) * 4) * 4;
    }
    uint32_t boff4;
    {
        const int row = wn * 24 + ((lane >> 4) << 3) + (lane & 7);
        boff4 = (uint32_t)(ATILE_U + row * AROWU + ((lane >> 3) & 1) * 4) * 4;
    }
    uint32_t boff2;
    {
        const int row = wn * 24 + 16 + (lane & 7);
        boff2 = (uint32_t)(ATILE_U + row * AROWU + ((lane >> 3) & 1) * 4) * 4;
    }

    float acc[4][3][4];
    #pragma unroll
    for (int m = 0; m < 4; m++)
        #pragma unroll
        for (int n = 0; n < 3; n++)
            #pragma unroll
            for (int r = 0; r < 4; r++) acc[m][n][r] = 0.f;

    #pragma unroll
    for (int s = 0; s < 3; s++) {
        const int k0 = s * KSTEP;
        const uint32_t ab = smbase + (uint32_t)(s * STAGE_U) * 4;
        const uint32_t bbs = ab + ATILE_U * 4;
        #pragma unroll
        for (int j = 0; j < 3; j++) {
            const int c = tid + 256 * j;
            const int r = c / 6, sg = c - r * 6;
            cp16(ab + (uint32_t)(r * AROWU + sg * 4) * 4, gA + (size_t)r * KDIM + k0 + sg * 8);
        }
        #pragma unroll
        for (int j = 0; j < 3; j++) {
            const int c = tid + 256 * j;
            if (c < BCHUNKS) {
                const int r = c / 6, sg = c - r * 6;
                cp16(bbs + (uint32_t)(r * AROWU + sg * 4) * 4, gB + (size_t)r * KDIM + k0 + sg * 8);
            }
        }
        cp_commit();
    }

    for (int it = 0; it < NKIT; it++) {
        cp_wait2();
        __syncthreads();

        if (it + 3 < NKIT) {
            const int s = (it + 3) & 3;
            const int k0 = (it + 3) * KSTEP;
            const uint32_t ab = smbase + (uint32_t)(s * STAGE_U) * 4;
            const uint32_t bbs = ab + ATILE_U * 4;
            #pragma unroll
            for (int j = 0; j < 3; j++) {
                const int c = tid + 256 * j;
                const int r = c / 6, sg = c - r * 6;
                cp16(ab + (uint32_t)(r * AROWU + sg * 4) * 4, gA + (size_t)r * KDIM + k0 + sg * 8);
            }
            #pragma unroll
            for (int j = 0; j < 3; j++) {
                const int c = tid + 256 * j;
                if (c < BCHUNKS) {
                    const int r = c / 6, sg = c - r * 6;
                    cp16(bbs + (uint32_t)(r * AROWU + sg * 4) * 4, gB + (size_t)r * KDIM + k0 + sg * 8);
                }
            }
        }
        cp_commit();

        const uint32_t stoff = smbase + (uint32_t)((it & 3) * STAGE_U) * 4;

        #pragma unroll
        for (int kk = 0; kk < 3; kk++) {
            const uint32_t kb = stoff + kk * 32;
            uint32_t afr[4][4];
            #pragma unroll
            for (int m = 0; m < 4; m++)
                ldsm4(afr[m], kb + aoff[m]);
            uint32_t bfr[3][2];
            {
                uint32_t r4[4];
                ldsm4(r4, kb + boff4);
                bfr[0][0] = r4[0]; bfr[0][1] = r4[1];
                bfr[1][0] = r4[2]; bfr[1][1] = r4[3];
                ldsm2(bfr[2], kb + boff2);
            }
            #pragma unroll
            for (int m = 0; m < 4; m++)
                #pragma unroll
                for (int n = 0; n < 3; n++)
                    mma_f16(acc[m][n], afr[m], bfr[n]);
        }
    }

    const float a0 = g_att[2 * b], a1 = g_att[2 * b + 1];
    #pragma unroll
    for (int m = 0; m < 4; m++) {
        const int co_lo = co0 + wm * 64 + m * 16 + g;
        const int co_hi = co_lo + 8;
        const float bias_lo = a0 * cb[co_lo] + a1 * eb[co_lo];
        const float bias_hi = a0 * cb[co_hi] + a1 * eb[co_hi];
        float* op_lo = out + ((size_t)b * COUT + co_lo) * PDIM;
        float* op_hi = out + ((size_t)b * COUT + co_hi) * PDIM;
        #pragma unroll
        for (int n = 0; n < 3; n++) {
            const int p = p0 + wn * 24 + n * 8 + t * 2;
            if (p < PDIM) {
                float2 v0 = make_float2(acc[m][n][0] + bias_lo, acc[m][n][1] + bias_lo);
                float2 v1 = make_float2(acc[m][n][2] + bias_hi, acc[m][n][3] + bias_hi);
                *(float2*)(op_lo + p) = v0;
                *(float2*)(op_hi + p) = v1;
            }
        }
    }
}

// ---------------------------------------------------------------------------
// Host launch: R12 fork topology (att branch overlaps im2col), full batch.
// ---------------------------------------------------------------------------
extern "C" void kernel_launch(void* const* d_in, const int* in_sizes, int n_in,
                              void* d_out, int out_size) {
    (void)in_sizes; (void)n_in; (void)out_size;
    const float* x  = (const float*)d_in[0];
    const float* wc = (const float*)d_in[1];
    const float* cb = (const float*)d_in[2];
    const float* we = (const float*)d_in[3];
    const float* eb = (const float*)d_in[4];
    const float* w1 = (const float*)d_in[5];
    const float* w2 = (const float*)d_in[6];
    float* out = (float*)d_out;

    static cudaStream_t s2 = nullptr;
    static cudaEvent_t ev_root = nullptr, ev_join = nullptr;
    if (s2 == nullptr) {
        cudaStreamCreateWithFlags(&s2, cudaStreamNonBlocking);
        cudaEventCreateWithFlags(&ev_root, cudaEventDisableTiming);
        cudaEventCreateWithFlags(&ev_join, cudaEventDisableTiming);
        cudaFuncSetAttribute(gemm_kernel,
                             cudaFuncAttributeMaxDynamicSharedMemorySize, SMEM_B);
    }

    cudaEventRecord(ev_root, 0);
    cudaStreamWaitEvent(s2, ev_root, 0);

    pool_kernel<<<dim3(CIN, BB), 256, 0, s2>>>(x);
    att_kernel<<<1, 256, 0, s2>>>(w1, w2);
    wmix_kernel<<<dim3(COUT, BB), 256, 0, s2>>>(wc, we);

    im2col_kernel<<<dim3(HO / OHB, 4, BB), 256>>>(x);

    cudaEventRecord(ev_join, s2);
    cudaStreamWaitEvent(0, ev_join, 0);
    gemm_kernel<<<dim3(2 * NPT, BB), 256, SMEM_B>>>(cb, eb, out);
}